// round 8
// baseline (speedup 1.0000x reference)
#include <cuda_runtime.h>
#include <cuda_fp16.h>
#include <cstdint>
#include <cstddef>

// Problem dims
#define NB 8
#define NS 2048
#define ND 1536
#define NH 8
#define NT 2048

// GEMM tiling: CTA tile 64(M) x 128(N), BK=64, 256 threads, 3-stage, 3 CTA/SM
#define BM 64
#define BN 128
#define BK 64
#define NCHUNK (ND / BK)         // 24
#define NSTAGE 3
#define A_TILE_B 8192            // 64 rows * 128 bytes
#define B_TILE_B 16384           // 128 rows * 128 bytes
#define STAGE_B (A_TILE_B + B_TILE_B)       // 24KB
#define SMEM_DYN (NSTAGE * STAGE_B + 1024)  // ~73.7KB -> 3 CTAs/SM

__constant__ int c_num_tracks[NH] = {128, 256, 512, 1024, 2048, 64, 32, 1024};

// fp32 -> fp16 scratch (device globals: allocation-free rule)
__device__ __align__(256) __half g_XH[(size_t)NB * NS * ND];
__device__ __align__(256) __half g_WH[(size_t)NH * NT * ND];   // [h][t][d]
__device__ int g_head_used[NH];

static __device__ __forceinline__ uint32_t s2u(const void* p) {
    return (uint32_t)__cvta_generic_to_shared(p);
}

#define LDSM4(r, addr) \
    asm volatile("ldmatrix.sync.aligned.m8n8.x4.shared.b16 {%0,%1,%2,%3}, [%4];" \
                 : "=r"((r)[0]), "=r"((r)[1]), "=r"((r)[2]), "=r"((r)[3]) \
                 : "r"(addr))

// fp16-accumulate MMA: 2-reg acc (packed half2 pairs), full-rate on sm_103
#define MMA16816F16(c, a, b0, b1) \
    asm volatile("mma.sync.aligned.m16n8k16.row.col.f16.f16.f16.f16 " \
                 "{%0,%1}, {%2,%3,%4,%5}, {%6,%7}, {%0,%1};" \
                 : "+r"((c)[0]), "+r"((c)[1]) \
                 : "r"((a)[0]), "r"((a)[1]), "r"((a)[2]), "r"((a)[3]), \
                   "r"(b0), "r"(b1))

// ---------------------------------------------------------------------------
// Prep 0: mark which heads are actually selected (head_idx lives on device)
// ---------------------------------------------------------------------------
__global__ void mark_heads_kernel(const int* __restrict__ head_idx) {
    int t = threadIdx.x;
    if (t < NH) g_head_used[t] = 0;
    __syncthreads();
    if (t < NB) g_head_used[head_idx[t]] = 1;
}

// ---------------------------------------------------------------------------
// Prep 1: x (fp32) -> XH (fp16), layout [b][s][d]
// ---------------------------------------------------------------------------
__global__ void convert_x_kernel(const float4* __restrict__ x, int n4) {
    int i = blockIdx.x * blockDim.x + threadIdx.x;
    if (i >= n4) return;
    float4 v = x[i];
    __half2* XH2 = reinterpret_cast<__half2*>(g_XH);
    XH2[2 * (size_t)i + 0] = __floats2half2_rn(v.x, v.y);
    XH2[2 * (size_t)i + 1] = __floats2half2_rn(v.z, v.w);
}

// ---------------------------------------------------------------------------
// Prep 2: W [h][d][t] fp32 -> WH [h][t][d] fp16 (transpose)
// Skips heads not selected, and t-blocks beyond the tile-rounded track count.
// ---------------------------------------------------------------------------
__global__ void convert_w_kernel(const float* __restrict__ W) {
    __shared__ float t[32][33];
    int h  = blockIdx.z;
    int n0 = blockIdx.x * 32;   // t dimension
    if (!g_head_used[h]) return;
    int ntr_pad = ((c_num_tracks[h] + BN - 1) / BN) * BN;
    if (n0 >= ntr_pad) return;
    int k0 = blockIdx.y * 32;   // d dimension
#pragma unroll
    for (int j = 0; j < 4; j++) {
        int k = k0 + threadIdx.y + j * 8;
        t[threadIdx.y + j * 8][threadIdx.x] =
            W[((size_t)h * ND + k) * NT + n0 + threadIdx.x];
    }
    __syncthreads();
#pragma unroll
    for (int j = 0; j < 4; j++) {
        int n = n0 + threadIdx.y + j * 8;
        float v = t[threadIdx.x][threadIdx.y + j * 8];
        g_WH[((size_t)h * NT + n) * ND + k0 + threadIdx.x] = __float2half(v);
    }
}

// ---------------------------------------------------------------------------
// Main GEMM: CTA computes 64x128 fp32 tile: D = X@W^T
// fp16 MMA accumulation within each K=64 chunk (full-rate HMMA), drained to
// fp32 registers once per chunk. Tiles beyond num_tracks[head] zero-store.
// 3-stage cp.async pipeline, one __syncthreads/iter. 8 warps 2(M)x4(N),
// warp tile 32x32. 3 CTAs/SM.
// ---------------------------------------------------------------------------
__global__ void __launch_bounds__(256, 3)
gemm_kernel(const int* __restrict__ head_idx,
            const float* __restrict__ bias,
            float* __restrict__ out)
{
    __shared__ float sbias[BN];
    extern __shared__ char smem_raw[];

    const int tid = threadIdx.x;
    const int wid = tid >> 5;
    const int lid = tid & 31;
    const int bz  = blockIdx.z;
    const int m0  = blockIdx.y * BM;
    const int n0  = blockIdx.x * BN;
    const int h   = head_idx[bz];

    if (n0 >= c_num_tracks[h]) {
        // Entire tile is zero (masked W and b). Pure store, no compute.
        float4 z = make_float4(0.f, 0.f, 0.f, 0.f);
        float4* op = reinterpret_cast<float4*>(
            out + ((size_t)bz * NS + m0) * NT + n0);
        const int c4 = BN / 4;                  // 32 float4 per row
#pragma unroll 4
        for (int i = tid; i < BM * c4; i += 256) {
            int row = i >> 5;
            int col = i & 31;
            op[(size_t)row * (NT / 4) + col] = z;
        }
        return;
    }

    const uint32_t sbase = (s2u(smem_raw) + 1023u) & ~1023u;

    if (tid < BN) sbias[tid] = bias[h * NT + n0 + tid];

    const __half* Xh = g_XH + ((size_t)bz * NS + m0) * ND;
    const __half* Wh = g_WH + ((size_t)h * NT + n0) * ND;

    // --- load one K-chunk (A 64x128B, B 128x128B) via cp.async
    auto load_chunk = [&](int c, int stage) {
        const int kb = c * BK;
        const uint32_t stb = sbase + (uint32_t)stage * STAGE_B;
#pragma unroll
        for (int part = 0; part < 2; part++) {
            int within = part * 256 + tid;        // 0..511
            int row = within >> 3;
            int seg = within & 7;
            uint32_t boff = (uint32_t)(row * 128 + seg * 16);
            uint32_t sw = boff ^ ((boff >> 3) & 0x70);
            const __half* ga = Xh + (size_t)row * ND + kb + seg * 8;
            asm volatile("cp.async.cg.shared.global [%0], [%1], 16;"
                         :: "r"(stb + sw), "l"(ga) : "memory");
        }
#pragma unroll
        for (int part = 0; part < 4; part++) {
            int within = part * 256 + tid;        // 0..1023
            int row = within >> 3;
            int seg = within & 7;
            uint32_t boff = (uint32_t)(row * 128 + seg * 16);
            uint32_t sw = boff ^ ((boff >> 3) & 0x70);
            const __half* gb = Wh + (size_t)row * ND + kb + seg * 8;
            asm volatile("cp.async.cg.shared.global [%0], [%1], 16;"
                         :: "r"(stb + A_TILE_B + sw), "l"(gb) : "memory");
        }
        asm volatile("cp.async.commit_group;" ::: "memory");
    };

    // Warp tiling: 2 (M) x 4 (N) warps; warp tile 32 x 32
    const int wm = wid >> 2;          // 0..1
    const int wn = wid & 3;           // 0..3

    const int rA = lid & 15;
    const int cA = lid >> 4;
    const int rB = (lid & 7) + ((lid >> 4) << 3);
    const int cB = (lid >> 3) & 1;
    const int rowA = wm * 32 + rA;    // smem row (A), +mt*16
    const int rowB = wn * 32 + rB;    // smem row (B), +np*16

    float acc[2][4][4];
#pragma unroll
    for (int i = 0; i < 2; i++)
#pragma unroll
        for (int j = 0; j < 4; j++)
#pragma unroll
            for (int q = 0; q < 4; q++) acc[i][j][q] = 0.0f;

    auto compute_chunk = [&](int stage) {
        const uint32_t stb = sbase + (uint32_t)stage * STAGE_B;
        const uint32_t aT = stb;
        const uint32_t bT = stb + A_TILE_B;
        // fp16 chunk accumulators (zeroed each chunk; |partials| << fp16 range)
        uint32_t cacc[2][4][2];
#pragma unroll
        for (int i = 0; i < 2; i++)
#pragma unroll
            for (int j = 0; j < 4; j++) { cacc[i][j][0] = 0u; cacc[i][j][1] = 0u; }
#pragma unroll
        for (int kh = 0; kh < 4; kh++) {
            uint32_t ah[2][4], bh[4][2];
#pragma unroll
            for (int mt = 0; mt < 2; mt++) {
                uint32_t chunk = (uint32_t)((2 * kh + cA) ^ (rowA & 7));
                uint32_t off = (uint32_t)(rowA + mt * 16) * 128 + (chunk << 4);
                LDSM4(ah[mt], aT + off);
            }
#pragma unroll
            for (int np = 0; np < 2; np++) {
                uint32_t chunk = (uint32_t)((2 * kh + cB) ^ (rowB & 7));
                uint32_t addr = bT + (uint32_t)(rowB + np * 16) * 128 + (chunk << 4);
                uint32_t r[4];
                LDSM4(r, addr);
                bh[np * 2][0]     = r[0]; bh[np * 2][1]     = r[1];
                bh[np * 2 + 1][0] = r[2]; bh[np * 2 + 1][1] = r[3];
            }
#pragma unroll
            for (int mt = 0; mt < 2; mt++)
#pragma unroll
                for (int nt = 0; nt < 4; nt++)
                    MMA16816F16(cacc[mt][nt], ah[mt], bh[nt][0], bh[nt][1]);
        }
        // Drain chunk partials (fp16) into fp32 accumulators
#pragma unroll
        for (int mt = 0; mt < 2; mt++)
#pragma unroll
            for (int nt = 0; nt < 4; nt++) {
                float2 lo = __half22float2(
                    *reinterpret_cast<const __half2*>(&cacc[mt][nt][0]));
                float2 hi = __half22float2(
                    *reinterpret_cast<const __half2*>(&cacc[mt][nt][1]));
                acc[mt][nt][0] += lo.x; acc[mt][nt][1] += lo.y;
                acc[mt][nt][2] += hi.x; acc[mt][nt][3] += hi.y;
            }
    };

    // Prologue: fill first two stages
    load_chunk(0, 0);
    load_chunk(1, 1);

#pragma unroll 1
    for (int k = 0; k < NCHUNK; k++) {
        // Wait for chunk k (leave at most the k+1 group outstanding)
        if (k < NCHUNK - 1) asm volatile("cp.async.wait_group 1;" ::: "memory");
        else                asm volatile("cp.async.wait_group 0;" ::: "memory");
        __syncthreads();
        // Stage (k+2)%3 == (k-1)%3: consumed at iter k-1; the barrier above
        // ordered every warp past compute(k-1), so overwriting is safe.
        if (k + 2 < NCHUNK) load_chunk(k + 2, (k + 2) % NSTAGE);
        compute_chunk(k % NSTAGE);
    }

    // Epilogue: bias + store
#pragma unroll
    for (int mt = 0; mt < 2; mt++) {
#pragma unroll
        for (int nt = 0; nt < 4; nt++) {
            int r0 = m0 + wm * 32 + mt * 16 + (lid >> 2);
            int c  = wn * 32 + nt * 8 + (lid & 3) * 2;
            float b0 = sbias[c], b1 = sbias[c + 1];
            float* p0 = out + ((size_t)bz * NS + r0) * NT + n0 + c;
            float* p1 = p0 + 8 * NT;
            float2 v;
            v.x = acc[mt][nt][0] + b0; v.y = acc[mt][nt][1] + b1;
            *reinterpret_cast<float2*>(p0) = v;
            v.x = acc[mt][nt][2] + b0; v.y = acc[mt][nt][3] + b1;
            *reinterpret_cast<float2*>(p1) = v;
        }
    }
}

// ---------------------------------------------------------------------------
extern "C" void kernel_launch(void* const* d_in, const int* in_sizes, int n_in,
                              void* d_out, int out_size) {
    const float* x        = (const float*)d_in[0];
    const int*   head_idx = (const int*)d_in[1];
    const float* W        = (const float*)d_in[2];
    const float* bias     = (const float*)d_in[3];
    float*       out      = (float*)d_out;
    (void)in_sizes; (void)n_in; (void)out_size;

    static bool attr_set = false;
    if (!attr_set) {
        cudaFuncSetAttribute(gemm_kernel,
                             cudaFuncAttributeMaxDynamicSharedMemorySize, SMEM_DYN);
        attr_set = true;
    }

    const int n4 = NB * NS * ND / 4;
    mark_heads_kernel<<<1, 32>>>(head_idx);
    convert_x_kernel<<<(n4 + 255) / 256, 256>>>((const float4*)x, n4);
    convert_w_kernel<<<dim3(NT / 32, ND / 32, NH), dim3(32, 8)>>>(W);
    gemm_kernel<<<dim3(NT / BN, NS / BM, NB), 256, SMEM_DYN>>>(head_idx, bias, out);
}

// round 9
// speedup vs baseline: 1.2895x; 1.2895x over previous
#include <cuda_runtime.h>
#include <cuda_fp16.h>
#include <cstdint>
#include <cstddef>

// Problem dims
#define NB 8
#define NS 2048
#define ND 1536
#define NH 8
#define NT 2048

// GEMM tiling: CTA 64(M) x 128(N), BK=64, 128 threads (4 warps, 32x64 warp
// tile), 3-stage cp.async, 3 CTAs/SM.
#define BM 64
#define BN 128
#define BK 64
#define NCHUNK (ND / BK)         // 24
#define NSTAGE 3
#define A_TILE_B 8192            // 64 rows * 128 bytes
#define B_TILE_B 16384           // 128 rows * 128 bytes
#define STAGE_B (A_TILE_B + B_TILE_B)       // 24KB
#define SMEM_DYN (NSTAGE * STAGE_B + 256)   // ~72.2KB -> 3 CTAs/SM

__constant__ int c_num_tracks[NH] = {128, 256, 512, 1024, 2048, 64, 32, 1024};

// fp32 -> fp16 scratch (device globals: allocation-free rule)
__device__ __align__(256) __half g_XH[(size_t)NB * NS * ND];
__device__ __align__(256) __half g_WH[(size_t)NH * NT * ND];   // [h][t][d]

static __device__ __forceinline__ uint32_t s2u(const void* p) {
    return (uint32_t)__cvta_generic_to_shared(p);
}

#define LDSM4(r, addr) \
    asm volatile("ldmatrix.sync.aligned.m8n8.x4.shared.b16 {%0,%1,%2,%3}, [%4];" \
                 : "=r"((r)[0]), "=r"((r)[1]), "=r"((r)[2]), "=r"((r)[3]) \
                 : "r"(addr))

#define MMA16816(c, a, b0, b1) \
    asm volatile("mma.sync.aligned.m16n8k16.row.col.f32.f16.f16.f32 " \
                 "{%0,%1,%2,%3}, {%4,%5,%6,%7}, {%8,%9}, {%0,%1,%2,%3};" \
                 : "+f"((c)[0]), "+f"((c)[1]), "+f"((c)[2]), "+f"((c)[3]) \
                 : "r"((a)[0]), "r"((a)[1]), "r"((a)[2]), "r"((a)[3]), \
                   "r"(b0), "r"(b1))

// ---------------------------------------------------------------------------
// Fused prep: blocks [0, XBLK) convert x -> fp16; blocks [XBLK, ...) transpose
// W [h][d][t] fp32 -> WH [h][t][d] fp16 (only selected heads / live t-range).
// ---------------------------------------------------------------------------
#define XN4 (NB * NS * ND / 4)      // float4 elements of x
#define XBLK (XN4 / 256)            // 12288 x-blocks (256 thr each)
#define WNX (NT / 32)               // 64
#define WNY (ND / 32)               // 48
#define WBLK_PER_H (WNX * WNY)      // 3072

__global__ void prep_kernel(const float4* __restrict__ x,
                            const float* __restrict__ W,
                            const int* __restrict__ head_idx) {
    int b = blockIdx.x;
    if (b < XBLK) {
        int i = b * 256 + threadIdx.x;
        float4 v = x[i];
        __half2* XH2 = reinterpret_cast<__half2*>(g_XH);
        XH2[2 * (size_t)i + 0] = __floats2half2_rn(v.x, v.y);
        XH2[2 * (size_t)i + 1] = __floats2half2_rn(v.z, v.w);
        return;
    }
    // --- W transpose block ---
    int wb = b - XBLK;
    int h  = wb / WBLK_PER_H;
    int r  = wb % WBLK_PER_H;
    int n0 = (r % WNX) * 32;    // t dimension
    int k0 = (r / WNX) * 32;    // d dimension

    bool used = false;
#pragma unroll
    for (int i = 0; i < NB; i++) used |= (head_idx[i] == h);
    if (!used) return;
    int ntr_pad = ((c_num_tracks[h] + BN - 1) / BN) * BN;
    if (n0 >= ntr_pad) return;

    __shared__ float t[32][33];
    int tx = threadIdx.x & 31;
    int ty = threadIdx.x >> 5;   // 0..7
#pragma unroll
    for (int j = 0; j < 4; j++) {
        int k = k0 + ty + j * 8;
        t[ty + j * 8][tx] = W[((size_t)h * ND + k) * NT + n0 + tx];
    }
    __syncthreads();
#pragma unroll
    for (int j = 0; j < 4; j++) {
        int n = n0 + ty + j * 8;
        float v = t[tx][ty + j * 8];
        g_WH[((size_t)h * NT + n) * ND + k0 + tx] = __float2half(v);
    }
}

// ---------------------------------------------------------------------------
// Main GEMM: CTA computes 64x128 fp32 tile: D = X@W^T (fp16 in, fp32 accum)
// Tiles beyond num_tracks[head] zero-store and exit.
// 3-stage cp.async pipeline, one __syncthreads/iter.
// 4 warps in 2(M)x2(N) grid, warp tile 32x64, explicit kh double-buffering
// (LDSM of kh+1 issued before MMAs of kh -> smem/tensor overlap).
// ---------------------------------------------------------------------------
__global__ void __launch_bounds__(128, 3)
gemm_kernel(const int* __restrict__ head_idx,
            const float* __restrict__ bias,
            float* __restrict__ out)
{
    __shared__ float sbias[BN];
    extern __shared__ char smem_raw[];

    const int tid = threadIdx.x;
    const int wid = tid >> 5;
    const int lid = tid & 31;
    const int bz  = blockIdx.z;
    const int m0  = blockIdx.y * BM;
    const int n0  = blockIdx.x * BN;
    const int h   = head_idx[bz];

    if (n0 >= c_num_tracks[h]) {
        // Entire tile is zero (masked W and b). Pure store, no compute.
        float4 z = make_float4(0.f, 0.f, 0.f, 0.f);
        float4* op = reinterpret_cast<float4*>(
            out + ((size_t)bz * NS + m0) * NT + n0);
#pragma unroll 4
        for (int i = tid; i < BM * (BN / 4); i += 128) {
            int row = i >> 5;
            int col = i & 31;
            op[(size_t)row * (NT / 4) + col] = z;
        }
        return;
    }

    const uint32_t sbase = (s2u(smem_raw) + 255u) & ~255u;

    if (tid < BN) sbias[tid] = bias[h * NT + n0 + tid];

    const __half* Xh = g_XH + ((size_t)bz * NS + m0) * ND;
    const __half* Wh = g_WH + ((size_t)h * NT + n0) * ND;

    // --- load one K-chunk (A 64x128B, B 128x128B) via cp.async (128 thr)
    auto load_chunk = [&](int c, int stage) {
        const int kb = c * BK;
        const uint32_t stb = sbase + (uint32_t)stage * STAGE_B;
        // A: 512 16B ops, 4 per thread
#pragma unroll
        for (int part = 0; part < 4; part++) {
            int within = part * 128 + tid;        // 0..511
            int row = within >> 3;
            int seg = within & 7;
            uint32_t boff = (uint32_t)(row * 128 + seg * 16);
            uint32_t sw = boff ^ ((boff >> 3) & 0x70);
            const __half* ga = Xh + (size_t)row * ND + kb + seg * 8;
            asm volatile("cp.async.cg.shared.global [%0], [%1], 16;"
                         :: "r"(stb + sw), "l"(ga) : "memory");
        }
        // B: 1024 16B ops, 8 per thread
#pragma unroll
        for (int part = 0; part < 8; part++) {
            int within = part * 128 + tid;        // 0..1023
            int row = within >> 3;
            int seg = within & 7;
            uint32_t boff = (uint32_t)(row * 128 + seg * 16);
            uint32_t sw = boff ^ ((boff >> 3) & 0x70);
            const __half* gb = Wh + (size_t)row * ND + kb + seg * 8;
            asm volatile("cp.async.cg.shared.global [%0], [%1], 16;"
                         :: "r"(stb + A_TILE_B + sw), "l"(gb) : "memory");
        }
        asm volatile("cp.async.commit_group;" ::: "memory");
    };

    // Warp tiling: 2 (M) x 2 (N) warps; warp tile 32 x 64
    const int wm = wid >> 1;          // 0..1
    const int wn = wid & 1;           // 0..1

    const int rA = lid & 15;
    const int cA = lid >> 4;
    const int rB = (lid & 7) + ((lid >> 4) << 3);
    const int cB = (lid >> 3) & 1;
    const int rowA = wm * 32 + rA;    // smem row (A), +mt*16
    const int rowB = wn * 64 + rB;    // smem row (B), +np*16

    float acc[2][8][4];
#pragma unroll
    for (int i = 0; i < 2; i++)
#pragma unroll
        for (int j = 0; j < 8; j++)
#pragma unroll
            for (int q = 0; q < 4; q++) acc[i][j][q] = 0.0f;

    // Double-buffered fragments (kh-level software pipeline)
    uint32_t ah[2][2][4], bh[2][8][2];

    auto ldsm_kh = [&](uint32_t aT, uint32_t bT, int kh, int buf) {
#pragma unroll
        for (int mt = 0; mt < 2; mt++) {
            uint32_t chunk = (uint32_t)((2 * kh + cA) ^ (rowA & 7));
            uint32_t off = (uint32_t)(rowA + mt * 16) * 128 + (chunk << 4);
            LDSM4(ah[buf][mt], aT + off);
        }
#pragma unroll
        for (int np = 0; np < 4; np++) {
            uint32_t chunk = (uint32_t)((2 * kh + cB) ^ (rowB & 7));
            uint32_t addr = bT + (uint32_t)(rowB + np * 16) * 128 + (chunk << 4);
            uint32_t r[4];
            LDSM4(r, addr);
            bh[buf][np * 2][0]     = r[0]; bh[buf][np * 2][1]     = r[1];
            bh[buf][np * 2 + 1][0] = r[2]; bh[buf][np * 2 + 1][1] = r[3];
        }
    };

    auto compute_chunk = [&](int stage) {
        const uint32_t stb = sbase + (uint32_t)stage * STAGE_B;
        const uint32_t aT = stb;
        const uint32_t bT = stb + A_TILE_B;
        ldsm_kh(aT, bT, 0, 0);
#pragma unroll
        for (int kh = 0; kh < 4; kh++) {
            // Prefetch next kh's fragments BEFORE this kh's MMA burst:
            // the 6 LDSM issues overlap the 32-MMA tensor burst.
            if (kh < 3) ldsm_kh(aT, bT, kh + 1, (kh + 1) & 1);
            int b = kh & 1;
#pragma unroll
            for (int mt = 0; mt < 2; mt++)
#pragma unroll
                for (int nt = 0; nt < 8; nt++)
                    MMA16816(acc[mt][nt], ah[b][mt], bh[b][nt][0], bh[b][nt][1]);
        }
    };

    // Prologue: fill first two stages
    load_chunk(0, 0);
    load_chunk(1, 1);

#pragma unroll 1
    for (int k = 0; k < NCHUNK; k++) {
        // Wait for chunk k (leave at most the k+1 group outstanding)
        if (k < NCHUNK - 1) asm volatile("cp.async.wait_group 1;" ::: "memory");
        else                asm volatile("cp.async.wait_group 0;" ::: "memory");
        __syncthreads();
        // Stage (k+2)%3 == (k-1)%3: consumed at iter k-1; the barrier above
        // ordered every warp past compute(k-1), so overwriting is safe.
        if (k + 2 < NCHUNK) load_chunk(k + 2, (k + 2) % NSTAGE);
        compute_chunk(k % NSTAGE);
    }

    // Epilogue: bias + store
#pragma unroll
    for (int mt = 0; mt < 2; mt++) {
#pragma unroll
        for (int nt = 0; nt < 8; nt++) {
            int r0 = m0 + wm * 32 + mt * 16 + (lid >> 2);
            int c  = wn * 64 + nt * 8 + (lid & 3) * 2;
            float b0 = sbias[c], b1 = sbias[c + 1];
            float* p0 = out + ((size_t)bz * NS + r0) * NT + n0 + c;
            float* p1 = p0 + 8 * NT;
            float2 v;
            v.x = acc[mt][nt][0] + b0; v.y = acc[mt][nt][1] + b1;
            *reinterpret_cast<float2*>(p0) = v;
            v.x = acc[mt][nt][2] + b0; v.y = acc[mt][nt][3] + b1;
            *reinterpret_cast<float2*>(p1) = v;
        }
    }
}

// ---------------------------------------------------------------------------
extern "C" void kernel_launch(void* const* d_in, const int* in_sizes, int n_in,
                              void* d_out, int out_size) {
    const float* x        = (const float*)d_in[0];
    const int*   head_idx = (const int*)d_in[1];
    const float* W        = (const float*)d_in[2];
    const float* bias     = (const float*)d_in[3];
    float*       out      = (float*)d_out;
    (void)in_sizes; (void)n_in; (void)out_size;

    static bool attr_set = false;
    if (!attr_set) {
        cudaFuncSetAttribute(gemm_kernel,
                             cudaFuncAttributeMaxDynamicSharedMemorySize, SMEM_DYN);
        attr_set = true;
    }

    prep_kernel<<<XBLK + NH * WBLK_PER_H, 256>>>((const float4*)x, W, head_idx);
    gemm_kernel<<<dim3(NT / BN, NS / BM, NB), 128, SMEM_DYN>>>(head_idx, bias, out);
}